// round 10
// baseline (speedup 1.0000x reference)
#include <cuda_runtime.h>
#include <cuda_fp16.h>
#include <cstdint>

typedef unsigned int u32;

#define H 256
#define W 256
#define RAD 5
#define KS 11
#define PLANE (H*W)

#define TW 32
#define TH 8
#define NTEAM 3
#define HLW (TW + 2*RAD)   // 42
#define HLH (TH + 2*RAD)   // 18
#define SSTR 43            // padded row stride
#define NS (HLH * SSTR)    // 774

#define QS 8.0f            // int8 quantization step for the prefilter
#define QTHR 1792          // live iff d2_int <= QTHR (d2_int > QTHR => mahal(EXS) > 25)

__device__ __forceinline__ u32 pk(float a, float b) {
    __half2 h = __floats2half2_rn(a, b);
    return *reinterpret_cast<u32*>(&h);
}
__device__ __forceinline__ __half2 uh(u32 u) {
    return *reinterpret_cast<__half2*>(&u);
}
__device__ __forceinline__ int q8(float x) {
    return __float2int_rn(fminf(fmaxf(x * QS, -127.0f), 127.0f));
}

__global__ __launch_bounds__(768, 2) void jbf_kernel(
    const float* __restrict__ img, const float* __restrict__ gui,
    const float* __restrict__ est, const float* __restrict__ var,
    const float* __restrict__ sig, float* __restrict__ out, float K)
{
    // Fast path touches ONLY sQ4 (one LDS.64 per tap).
    __shared__ uint2  sQ4[NS];   // {int8 q of 4 strong channels, S4 = sum q^2}
    __shared__ uint4  sG[NS];    // 8 guidance halves, prescaled by sqrt(0.7213*sig_inv)
    __shared__ uint4  sMR[NS];   // {h2(e0,e1), h2(Kv0,Kv1), h2(Kv2,e2), img2 bits}
    __shared__ float2 sI2[NS];   // img ch0, ch1 (fp32)
    __shared__ float4 sRed[NTEAM - 1][TH * TW];

    const int bx = blockIdx.x * TW, by = blockIdx.y * TH;
    const int tx = threadIdx.x, ty = threadIdx.y, tz = threadIdx.z;
    const int tid = tx + TW * (ty + TH * tz);

    // fold -0.5*log2(e) of the exp into the guidance prescale
    const float EXS = 0.72134752044f;
    const float rs0 = sqrtf(sig[0]  * EXS), rs1 = sqrtf(sig[9]  * EXS);
    const float rs2 = sqrtf(sig[18] * EXS), rs3 = sqrtf(sig[27] * EXS);
    const float rs4 = sqrtf(sig[36] * EXS), rs5 = sqrtf(sig[45] * EXS);
    const float rs6 = sqrtf(sig[54] * EXS), rs7 = sqrtf(sig[63] * EXS);

    // Fused halo fill with reflect padding (756 halo px, 768 threads: 1 pass)
    for (int i = tid; i < HLW * HLH; i += TW * TH * NTEAM) {
        int r = i / HLW, c = i - r * HLW;
        int gy = by + r - RAD, gx = bx + c - RAD;
        gy = (gy < 0) ? -gy : ((gy > H - 1) ? 2 * (H - 1) - gy : gy);
        gx = (gx < 0) ? -gx : ((gx > W - 1) ? 2 * (W - 1) - gx : gx);
        const int s = gy * W + gx;
        const int si = r * SSTR + c;

        const float s0 = gui[s]           * rs0, s1 = gui[s +   PLANE] * rs1;
        const float s2 = gui[s + 2*PLANE] * rs2, s3 = gui[s + 3*PLANE] * rs3;
        const float s4 = gui[s + 4*PLANE] * rs4, s5 = gui[s + 5*PLANE] * rs5;
        const float s6 = gui[s + 6*PLANE] * rs6, s7 = gui[s + 7*PLANE] * rs7;

        uint4 g;
        g.x = pk(s0, s1); g.y = pk(s2, s3); g.z = pk(s4, s5); g.w = pk(s6, s7);
        sG[si] = g;

        // int8 signature of the 4 strongest channels (sig_inv 50,50,50,10)
        const int q2v = q8(s2), q3v = q8(s3), q4v = q8(s4), q5v = q8(s5);
        uint2 q;
        q.x = (u32)(q2v & 0xFF) | ((u32)(q3v & 0xFF) << 8) |
              ((u32)(q4v & 0xFF) << 16) | ((u32)(q5v & 0xFF) << 24);
        q.y = (u32)__dp4a((int)q.x, (int)q.x, 0);
        sQ4[si] = q;

        const float e0 = est[s], e1 = est[s + PLANE], e2 = est[s + 2*PLANE];
        const float v0 = K * var[s], v1 = K * var[s + PLANE], v2 = K * var[s + 2*PLANE];
        uint4 mr;
        mr.x = pk(e0, e1);
        mr.y = pk(v0, v1);
        mr.z = pk(v2, e2);                                        // ch2: e2 in HIGH half
        mr.w = *reinterpret_cast<const u32*>(&img[s + 2*PLANE]);  // img ch2 bits
        sMR[si] = mr;

        float2 i2; i2.x = img[s]; i2.y = img[s + PLANE];
        sI2[si] = i2;
    }
    __syncthreads();

    const int cidx = (ty + RAD) * SSTR + (tx + RAD);
    const uint2 cq = sQ4[cidx];
    const int cQ4 = (int)cq.x;
    const int thrL = QTHR - (int)cq.y;   // live iff S4_n - 2*dot <= thrL
    const uint4 cg = sG[cidx];
    const __half2 cg0 = uh(cg.x), cg1 = uh(cg.y), cg2 = uh(cg.z), cg3 = uh(cg.w);
    const uint4 cmr = sMR[cidx];
    const __half2 cP = uh(cmr.x), cR = uh(cmr.y), cQ = uh(cmr.z);

    float a0 = 0.f, a1 = 0.f, a2 = 0.f, ws = 0.f;

    // Team tz handles dy = tz, tz+3, ...
    for (int dy = tz; dy < KS; dy += NTEAM) {
        const int base = (ty + dy) * SSTR + tx;

        // ---- Branchless prefilter for all 11 taps: 11 independent
        //      LDS.64+DP4A chains (full MLP), live bits collected per lane.
        //      live <=> partial int d2 <= QTHR <= means mahal could be < 25.
        //      Center & reflect-duplicate taps give d2 == 0 -> always live.
        u32 mask = 0;
#pragma unroll
        for (int dx = 0; dx < KS; dx++) {
            const uint2 nq = sQ4[base + dx];
            const int dot = __dp4a((int)nq.x, cQ4, 0);
            const int dpart = (int)nq.y - 2 * dot;     // = d2_int - cS4
            if (dpart <= thrL) mask |= (1u << dx);
        }
        // One warp-collective OR replaces 11 votes; result is warp-uniform.
        mask = __reduce_or_sync(0xFFFFFFFFu, mask);

        // ---- Full precise eval only for live taps (uniform bit loop, no divergence).
        while (mask) {
            const int dx = __ffs(mask) - 1;
            mask &= mask - 1;
            const int n = base + dx;

            const uint4 ng = sG[n];
            __half2 d, m2;
            d  = __hsub2(cg0, uh(ng.x)); m2 = __hmul2(d, d);
            d  = __hsub2(cg1, uh(ng.y)); m2 = __hfma2(d, d, m2);
            d  = __hsub2(cg2, uh(ng.z)); m2 = __hfma2(d, d, m2);
            d  = __hsub2(cg3, uh(ng.w)); m2 = __hfma2(d, d, m2);
            const float m = __half2float(__hadd(__low2half(m2), __high2half(m2)));

            float bl;
            {
                const float p = -m;
                asm("ex2.approx.ftz.f32 %0, %1;" : "=f"(bl) : "f"(p));
            }

            // Membership: d_c^2 < K*(v_ci + v_cj), 3 channels (== t < gamma_w)
            const uint4 nmr = sMR[n];
            const __half2 nP = uh(nmr.x), nR = uh(nmr.y), nQ = uh(nmr.z);
            const __half2 d01 = __hsub2(cP, nP);
            const __half2 s01 = __hadd2(cR, nR);
            const __half2 r01 = __hfma2(d01, d01, __hneg2(s01));           // signs @15,@31
            const __half2 dq  = __hsub2(cQ, nQ);                           // {dKv2, d_e2}
            const __half2 sq  = __hadd2(cQ, nQ);                           // {sKv2, ...}
            const __half2 r2h = __hfma2(dq, dq, __hneg2(__low2half2(sq))); // sign @31
            const u32 u01 = *reinterpret_cast<const u32*>(&r01);
            const u32 u2  = *reinterpret_cast<const u32*>(&r2h);
            const u32 allneg = u01 & (u01 << 16) & u2;

            u32 wmsk = (u32)((int)allneg >> 31);
            u32 wb = (*reinterpret_cast<const u32*>(&bl)) & wmsk;
            float w = *reinterpret_cast<const float*>(&wb);
            if (dx == RAD && dy == RAD) w = 1.0f;   // center forced to 1

            const float2 im = sI2[n];
            ws += w;
            a0 = fmaf(w, im.x, a0);
            a1 = fmaf(w, im.y, a1);
            a2 = fmaf(w, *reinterpret_cast<const float*>(&nmr.w), a2);
        }
    }

    // Cross-team reduction (teams 1..NTEAM-1 -> team 0)
    if (tz > 0) {
        float4 p; p.x = a0; p.y = a1; p.z = a2; p.w = ws;
        sRed[tz - 1][ty * TW + tx] = p;
    }
    __syncthreads();
    if (tz == 0) {
        const float4 p = sRed[0][ty * TW + tx];
        const float4 q = sRed[1][ty * TW + tx];
        a0 += p.x + q.x; a1 += p.y + q.y; a2 += p.z + q.z; ws += p.w + q.w;

        const float inv = 1.0f / fmaxf(ws, 1e-10f);
        const int o = (by + ty) * W + (bx + tx);
        out[o]           = a0 * inv;
        out[PLANE + o]   = a1 * inv;
        out[2*PLANE + o] = a2 * inv;
    }
}

extern "C" void kernel_launch(void* const* d_in, const int* in_sizes, int n_in,
                              void* d_out, int out_size) {
    const float* img = (const float*)d_in[0];   // [3,256,256]
    const float* gui = (const float*)d_in[1];   // [8,256,256]
    const float* est = (const float*)d_in[2];   // [3,256,256]
    const float* var = (const float*)d_in[3];   // [3,256,256]
    const float* sig = (const float*)d_in[4];   // [8,8]
    (void)in_sizes; (void)n_in;

    // membership: t < gamma  <=>  d^2 < gamma^2 * (vi+vj)
    const float K = 2.9110f * 2.9110f;

    dim3 block(TW, TH, NTEAM);          // 768 threads
    dim3 grid(W / TW, H / TH);          // 8 x 32 = 256 CTAs
    jbf_kernel<<<grid, block>>>(img, gui, est, var, sig, (float*)d_out, K);
}

// round 11
// speedup vs baseline: 1.4128x; 1.4128x over previous
#include <cuda_runtime.h>
#include <cuda_fp16.h>
#include <cstdint>

typedef unsigned int u32;

#define H 256
#define W 256
#define RAD 5
#define KS 11
#define PLANE (H*W)

#define TW 32
#define TH 8
#define NTEAM 3
#define HLW (TW + 2*RAD)   // 42
#define HLH (TH + 2*RAD)   // 18
#define SSTR 43            // padded row stride
#define NS (HLH * SSTR)    // 774

#define QS 8.0f            // int8 quantization step for the prefilter
#define QTHR 1792          // live iff d2_int <= QTHR (else mahal(EXS) > 25 guaranteed)

__device__ __forceinline__ u32 pk(float a, float b) {
    __half2 h = __floats2half2_rn(a, b);
    return *reinterpret_cast<u32*>(&h);
}
__device__ __forceinline__ __half2 uh(u32 u) {
    return *reinterpret_cast<__half2*>(&u);
}
__device__ __forceinline__ int q8(float x) {
    return __float2int_rn(fminf(fmaxf(x * QS, -127.0f), 127.0f));
}

__global__ __launch_bounds__(768, 2) void jbf_kernel(
    const float* __restrict__ img, const float* __restrict__ gui,
    const float* __restrict__ est, const float* __restrict__ var,
    const float* __restrict__ sig, float* __restrict__ out, float K)
{
    __shared__ uint2  sQ4[NS];   // {int8 q of 4 strong channels, S4 = sum q^2}
    __shared__ uint4  sG[NS];    // 8 guidance halves, prescaled by sqrt(0.7213*sig_inv)
    __shared__ uint4  sMR[NS];   // {h2(e0,e1), h2(Kv0,Kv1), h2(Kv2,e2), img2 bits}
    __shared__ float2 sI2[NS];   // img ch0, ch1 (fp32)
    __shared__ float4 sRed[NTEAM - 1][TH * TW];

    const int bx = blockIdx.x * TW, by = blockIdx.y * TH;
    const int tx = threadIdx.x, ty = threadIdx.y, tz = threadIdx.z;
    const int tid = tx + TW * (ty + TH * tz);

    // fold -0.5*log2(e) of the exp into the guidance prescale
    const float EXS = 0.72134752044f;
    const float rs0 = sqrtf(sig[0]  * EXS), rs1 = sqrtf(sig[9]  * EXS);
    const float rs2 = sqrtf(sig[18] * EXS), rs3 = sqrtf(sig[27] * EXS);
    const float rs4 = sqrtf(sig[36] * EXS), rs5 = sqrtf(sig[45] * EXS);
    const float rs6 = sqrtf(sig[54] * EXS), rs7 = sqrtf(sig[63] * EXS);

    // Fused halo fill with reflect padding (756 halo px, 768 threads: 1 pass)
    for (int i = tid; i < HLW * HLH; i += TW * TH * NTEAM) {
        int r = i / HLW, c = i - r * HLW;
        int gy = by + r - RAD, gx = bx + c - RAD;
        gy = (gy < 0) ? -gy : ((gy > H - 1) ? 2 * (H - 1) - gy : gy);
        gx = (gx < 0) ? -gx : ((gx > W - 1) ? 2 * (W - 1) - gx : gx);
        const int s = gy * W + gx;
        const int si = r * SSTR + c;

        const float s0 = gui[s]           * rs0, s1 = gui[s +   PLANE] * rs1;
        const float s2 = gui[s + 2*PLANE] * rs2, s3 = gui[s + 3*PLANE] * rs3;
        const float s4 = gui[s + 4*PLANE] * rs4, s5 = gui[s + 5*PLANE] * rs5;
        const float s6 = gui[s + 6*PLANE] * rs6, s7 = gui[s + 7*PLANE] * rs7;

        uint4 g;
        g.x = pk(s0, s1); g.y = pk(s2, s3); g.z = pk(s4, s5); g.w = pk(s6, s7);
        sG[si] = g;

        // int8 signature of the 4 strongest channels (sig_inv 50,50,50,10)
        const int q2v = q8(s2), q3v = q8(s3), q4v = q8(s4), q5v = q8(s5);
        uint2 q;
        q.x = (u32)(q2v & 0xFF) | ((u32)(q3v & 0xFF) << 8) |
              ((u32)(q4v & 0xFF) << 16) | ((u32)(q5v & 0xFF) << 24);
        q.y = (u32)__dp4a((int)q.x, (int)q.x, 0);
        sQ4[si] = q;

        const float e0 = est[s], e1 = est[s + PLANE], e2 = est[s + 2*PLANE];
        const float v0 = K * var[s], v1 = K * var[s + PLANE], v2 = K * var[s + 2*PLANE];
        uint4 mr;
        mr.x = pk(e0, e1);
        mr.y = pk(v0, v1);
        mr.z = pk(v2, e2);                                        // ch2: e2 in HIGH half
        mr.w = *reinterpret_cast<const u32*>(&img[s + 2*PLANE]);  // img ch2 bits
        sMR[si] = mr;

        float2 i2; i2.x = img[s]; i2.y = img[s + PLANE];
        sI2[si] = i2;
    }
    __syncthreads();

    const int cidx = (ty + RAD) * SSTR + (tx + RAD);
    const uint2 cq = sQ4[cidx];
    const int cQ4 = (int)cq.x;
    const int thrL = QTHR - (int)cq.y;   // live iff S4_n - 2*dot <= thrL
    const uint4 cg = sG[cidx];
    const __half2 cg0 = uh(cg.x), cg1 = uh(cg.y), cg2 = uh(cg.z), cg3 = uh(cg.w);
    const uint4 cmr = sMR[cidx];
    const __half2 cP = uh(cmr.x), cR = uh(cmr.y), cQ = uh(cmr.z);

    float a0 = 0.f, a1 = 0.f, a2 = 0.f, ws = 0.f;

    // Team tz handles dy = tz, tz+3, ...
    for (int dy = tz; dy < KS; dy += NTEAM) {
        const int base = (ty + dy) * SSTR + tx;
        const bool centerRow = (dy == RAD);

        // ---- Branchless PER-LANE prefilter: 11 independent LDS.64+DP4A
        //      chains (constant offsets, full MLP). Per-lane live bits only
        //      (~0.7/row worst case); no union reduction. Center & reflect-
        //      duplicate taps give d2_int == 0 -> always live.
        u32 mask = 0;
#pragma unroll
        for (int dx = 0; dx < KS; dx++) {
            const uint2 nq = sQ4[base + dx];
            const int dot = __dp4a((int)nq.x, cQ4, 0);
            const int dpart = (int)nq.y - 2 * dot;     // = d2_int - cS4
            mask |= (dpart <= thrL) ? (1u << dx) : 0u;
        }

        // ---- Each lane processes ITS OWN live taps; iterations = max live
        //      over lanes (~1 per row). Inactive lanes run the body with a
        //      safe index and weight forced to 0 (no divergence splits).
        while (__any_sync(0xFFFFFFFFu, mask)) {
            const bool act = (mask != 0u);
            const u32 actm = act ? 0xFFFFFFFFu : 0u;
            const int t = __ffs(mask) - 1;
            mask &= mask - 1u;
            const int dx = act ? t : RAD;
            const int n = base + dx;

            const uint4 ng = sG[n];
            __half2 d, m2;
            d  = __hsub2(cg0, uh(ng.x)); m2 = __hmul2(d, d);
            d  = __hsub2(cg1, uh(ng.y)); m2 = __hfma2(d, d, m2);
            d  = __hsub2(cg2, uh(ng.z)); m2 = __hfma2(d, d, m2);
            d  = __hsub2(cg3, uh(ng.w)); m2 = __hfma2(d, d, m2);
            const float m = __half2float(__hadd(__low2half(m2), __high2half(m2)));

            float bl;
            {
                const float p = -m;
                asm("ex2.approx.ftz.f32 %0, %1;" : "=f"(bl) : "f"(p));
            }

            // Membership: d_c^2 < K*(v_ci + v_cj), 3 channels (== t < gamma_w)
            const uint4 nmr = sMR[n];
            const __half2 nP = uh(nmr.x), nR = uh(nmr.y), nQ = uh(nmr.z);
            const __half2 d01 = __hsub2(cP, nP);
            const __half2 s01 = __hadd2(cR, nR);
            const __half2 r01 = __hfma2(d01, d01, __hneg2(s01));           // signs @15,@31
            const __half2 dq  = __hsub2(cQ, nQ);                           // {dKv2, d_e2}
            const __half2 sq  = __hadd2(cQ, nQ);                           // {sKv2, ...}
            const __half2 r2h = __hfma2(dq, dq, __hneg2(__low2half2(sq))); // sign @31
            const u32 u01 = *reinterpret_cast<const u32*>(&r01);
            const u32 u2  = *reinterpret_cast<const u32*>(&r2h);
            const u32 allneg = u01 & (u01 << 16) & u2;

            u32 wmsk = ((u32)((int)allneg >> 31)) & actm;
            u32 wb = (*reinterpret_cast<const u32*>(&bl)) & wmsk;
            float w = *reinterpret_cast<const float*>(&wb);
            if (centerRow && dx == RAD && act) w = 1.0f;   // center forced to 1

            const float2 im = sI2[n];
            ws += w;
            a0 = fmaf(w, im.x, a0);
            a1 = fmaf(w, im.y, a1);
            a2 = fmaf(w, *reinterpret_cast<const float*>(&nmr.w), a2);
        }
    }

    // Cross-team reduction (teams 1..NTEAM-1 -> team 0)
    if (tz > 0) {
        float4 p; p.x = a0; p.y = a1; p.z = a2; p.w = ws;
        sRed[tz - 1][ty * TW + tx] = p;
    }
    __syncthreads();
    if (tz == 0) {
        const float4 p = sRed[0][ty * TW + tx];
        const float4 q = sRed[1][ty * TW + tx];
        a0 += p.x + q.x; a1 += p.y + q.y; a2 += p.z + q.z; ws += p.w + q.w;

        const float inv = 1.0f / fmaxf(ws, 1e-10f);
        const int o = (by + ty) * W + (bx + tx);
        out[o]           = a0 * inv;
        out[PLANE + o]   = a1 * inv;
        out[2*PLANE + o] = a2 * inv;
    }
}

extern "C" void kernel_launch(void* const* d_in, const int* in_sizes, int n_in,
                              void* d_out, int out_size) {
    const float* img = (const float*)d_in[0];   // [3,256,256]
    const float* gui = (const float*)d_in[1];   // [8,256,256]
    const float* est = (const float*)d_in[2];   // [3,256,256]
    const float* var = (const float*)d_in[3];   // [3,256,256]
    const float* sig = (const float*)d_in[4];   // [8,8]
    (void)in_sizes; (void)n_in;

    // membership: t < gamma  <=>  d^2 < gamma^2 * (vi+vj)
    const float K = 2.9110f * 2.9110f;

    dim3 block(TW, TH, NTEAM);          // 768 threads
    dim3 grid(W / TW, H / TH);          // 8 x 32 = 256 CTAs
    jbf_kernel<<<grid, block>>>(img, gui, est, var, sig, (float*)d_out, K);
}